// round 5
// baseline (speedup 1.0000x reference)
#include <cuda_runtime.h>

#define FULLMASK 0xFFFFFFFFu

constexpr int Bn = 512;   // batch
constexpr int Tn = 512;   // time steps
constexpr int Cn = 128;   // classes (blank = C-1 = 127)
constexpr int Ln = 32;    // label length  (S = 2L+1 = 65 states)
constexpr float EPSF = 1e-7f;

// One warp per batch element. Lane l owns DP states 2l (blank) and 2l+1
// (label l); lane 31 additionally owns state 64 (final blank).
//
// Linear-probability forward algorithm in per-lane BLOCK FLOATING POINT:
// each lane keeps mantissas (me, mo, a64) and a private int exponent e,
// rescaled every step so the lane-max mantissa is in [1,2). Cross-lane terms
// are aligned with f = 2^(e_prev - e_new) built by integer exponent math.
// This keeps per-state dynamic range ~2^±2e9 (int exponent), with truncation
// only at ~2^-127 per pairwise add — same regime as log-domain logaddexp —
// while the inner loop stays free of transcendentals.
__global__ __launch_bounds__(32, 16)
void ctc_fwd_kernel(const int* __restrict__ y_true,
                    const float* __restrict__ y_pred,
                    float* __restrict__ out)
{
    const int b    = blockIdx.x;
    const int lane = threadIdx.x;           // 0..31

    // skip transition into odd state 2l+1 allowed iff l>0 and lab[l]!=lab[l-1]
    const int lab      = y_true[b * Ln + lane];
    const int lab_prev = __shfl_up_sync(FULLMASK, lab, 1);
    const float skipf  = (lane > 0 && lab != lab_prev) ? 1.0f : 0.0f;

    const float* __restrict__ row = y_pred + (size_t)b * Tn * Cn;

    // Delta-init: alpha_{-1}[s] = (s==0); one uniform recurrence step then
    // reproduces the reference's t=0 initialization exactly.
    float me  = (lane == 0) ? 1.0f : 0.0f;  // state 2l
    float mo  = 0.0f;                       // state 2l+1
    float a64 = 0.0f;                       // state 64 (lane 31 only meaningful)
    int   e   = 0;                          // per-lane binary exponent

    constexpr int U = 8;   // prefetch depth (2 LDG per lane per t)
    float pb[U], pl[U];

    #pragma unroll
    for (int j = 0; j < U; ++j) {
        const float* r = row + j * Cn;
        pb[j] = __ldcs(r + (Cn - 1)) + EPSF;   // blank prob (broadcast load)
        pl[j] = __ldcs(r + lab)      + EPSF;   // this lane's label prob
    }

    for (int chunk = 0; chunk < Tn / U; ++chunk) {
        float nb[U], nl[U];
        if (chunk + 1 < Tn / U) {
            const float* base = row + (size_t)(chunk + 1) * U * Cn;
            #pragma unroll
            for (int j = 0; j < U; ++j) {
                nb[j] = __ldcs(base + j * Cn + (Cn - 1)) + EPSF;
                nl[j] = __ldcs(base + j * Cn + lab)      + EPSF;
            }
        }

        #pragma unroll
        for (int j = 0; j < U; ++j) {
            // cross-lane exchange: neighbor's odd-state mantissa + exponent
            float mo_p = __shfl_up_sync(FULLMASK, mo, 1);
            int   e_p  = __shfl_up_sync(FULLMASK, e, 1);
            if (lane == 0) { mo_p = 0.0f; e_p = e; }

            // align both operands to the common scale e_new = max(e, e_p)
            const int en = max(e, e_p);
            const int ds = max(e  - en, -127);
            const int dp = max(e_p - en, -127);
            const float fs  = __int_as_float((127 + ds) << 23);  // 2^ds
            const float fpw = __int_as_float((127 + dp) << 23);  // 2^dp

            const float po  = fpw * mo_p;   // aligned alpha[2l-1]
            const float hs  = fs  * me;     // aligned alpha[2l]
            const float fso = fs  * mo;     // aligned alpha[2l+1]

            // even state 2l:  alpha[2l] + alpha[2l-1]              (no skip)
            float ne  = (hs + po) * pb[j];
            // odd state 2l+1: alpha[2l+1] + alpha[2l] + skip*alpha[2l-1]
            float no  = fmaf(skipf, po, hs + fso) * pl[j];
            // state 64:       alpha[64] + alpha[63]   (own-lane terms only)
            float n64 = fs * (a64 + mo) * pb[j];

            // per-lane rescale: pull the lane max back to [1,2)
            float mx = fmaxf(fmaxf(ne, no), n64);
            int   ex = (__float_as_int(mx) >> 23) - 127;   // floor(log2 mx); -127 if mx==0
            float rr = __int_as_float((127 - ex) << 23);   // 2^-ex (exact, finite)
            me  = ne  * rr;
            mo  = no  * rr;
            a64 = n64 * rr;
            e   = en + ex;
        }

        #pragma unroll
        for (int j = 0; j < U; ++j) { pb[j] = nb[j]; pl[j] = nl[j]; }
    }

    // loss = -ln(alpha_T[64] + alpha_T[63]); both live on lane 31 at scale 2^e
    if (lane == 31) {
        float msum = a64 + mo;
        out[b] = -(((float)e + log2f(msum)) * 0.69314718055994530942f);
    }
}

extern "C" void kernel_launch(void* const* d_in, const int* in_sizes, int n_in,
                              void* d_out, int out_size) {
    const int*   y_true;
    const float* y_pred;
    // identify inputs by size (y_true = 512*32 int32, y_pred = 512*512*128 f32)
    if (in_sizes[0] == Bn * Ln) {
        y_true = (const int*)d_in[0];
        y_pred = (const float*)d_in[1];
    } else {
        y_true = (const int*)d_in[1];
        y_pred = (const float*)d_in[0];
    }
    ctc_fwd_kernel<<<Bn, 32>>>(y_true, y_pred, (float*)d_out);
}

// round 13
// speedup vs baseline: 1.1244x; 1.1244x over previous
#include <cuda_runtime.h>

#define FULLMASK 0xFFFFFFFFu

constexpr int Bn = 512;   // batch
constexpr int Tn = 512;   // time steps
constexpr int Cn = 128;   // classes (blank = C-1 = 127)
constexpr int Ln = 32;    // label length  (S = 2L+1 = 65 states)
constexpr float EPSF = 1e-7f;

// One warp per batch element. Lane l owns DP states 2l (blank) and 2l+1
// (label l); lane 31 additionally owns state 64 (final blank).
//
// Linear-domain forward algorithm, per-lane block floating point. TWO
// timesteps fused per update. Shuffles carry PRE-rescale mantissas (ne,no)
// together with TWO exponents:
//   en    — the anchor the mantissas are expressed in (value reconstruction)
//   e     — post-rescale exponent = true lane magnitude (anchor formation)
// The new anchor is max over POST-rescale e's only. Using en in the max
// (Rounds 6-10) creates a running max over a backward cone: by lane 31 the
// anchor is ~220 binades stale, the -127 clamp zeroes the state, and the
// whole warp dies -> inf. e re-anchors to the true magnitude every step, so
// staleness is bounded at one iteration and the cone collapses.
__global__ __launch_bounds__(32, 8)
void ctc_fwd_kernel(const int* __restrict__ y_true,
                    const float* __restrict__ y_pred,
                    float* __restrict__ out)
{
    const int b    = blockIdx.x;
    const int lane = threadIdx.x;           // 0..31

    // skip into odd state 2l+1 allowed iff l>0 and lab[l]!=lab[l-1]
    const int   lab      = y_true[b * Ln + lane];
    const int   lab_prev = __shfl_up_sync(FULLMASK, lab, 1);
    const float sk       = (lane > 0 && lab != lab_prev) ? 1.0f : 0.0f;
    const float skm      = __shfl_up_sync(FULLMASK, sk, 1);  // neighbor's skip
    const bool  z1 = (lane == 0);
    const bool  z2 = (lane < 2);
    const bool  l31 = (lane == 31);

    const float* __restrict__ row = y_pred + (size_t)b * Tn * Cn;

    // Ring prefetch: 4 slots x 8 timesteps, prefetch distance 24 timesteps.
    float pbuf[4][8], plbuf[4][8];
    #pragma unroll
    for (int s = 0; s < 3; ++s)
        #pragma unroll
        for (int j = 0; j < 8; ++j) {
            const float* r = row + (s * 8 + j) * Cn;
            pbuf[s][j]  = __ldcs(r + (Cn - 1)) + EPSF;  // blank prob
            plbuf[s][j] = __ldcs(r + lab)      + EPSF;  // own label prob
        }

    // Delta-init: alpha_{-1}[s] = (s==0); uniform recurrence reproduces the
    // reference t=0 initialization exactly.
    float me  = z1 ? 1.0f : 0.0f;   // state 2l
    float mo  = 0.0f;               // state 2l+1
    float a64 = 0.0f;               // state 64 (meaningful on lane 31)
    int   e   = 0;                  // post-rescale exponent (true magnitude)

    // Shuffled previous-iteration quantities. Initial values are post-rescale
    // (scale e=0), so value-anchor and magnitude exponents coincide at 0.
    float s_no1 = __shfl_up_sync(FULLMASK, mo, 1);
    float s_ne1 = __shfl_up_sync(FULLMASK, me, 1);
    float s_no2 = __shfl_up_sync(FULLMASK, mo, 2);
    int   s_en1 = __shfl_up_sync(FULLMASK, e, 1);   // neighbor value anchor
    int   s_en2 = __shfl_up_sync(FULLMASK, e, 2);
    int   s_pe1 = __shfl_up_sync(FULLMASK, e, 1);   // neighbor true magnitude
    int   s_pe2 = __shfl_up_sync(FULLMASK, e, 2);
    float s_plm = __shfl_up_sync(FULLMASK, plbuf[0][0], 1);  // neighbor pl @ t0

    for (int big = 0; big < 16; ++big) {
        #pragma unroll
        for (int s = 0; s < 4; ++s) {
            // prefetch global slot (big*4+s)+3 into ring slot (s+3)&3
            const int tld = (big * 4 + s) * 8 + 24;
            if (tld < Tn) {
                const int ls = (s + 3) & 3;
                const float* base0 = row + (size_t)tld * Cn;
                #pragma unroll
                for (int j = 0; j < 8; ++j) {
                    pbuf[ls][j]  = __ldcs(base0 + j * Cn + (Cn - 1)) + EPSF;
                    plbuf[ls][j] = __ldcs(base0 + j * Cn + lab)      + EPSF;
                }
            }

            #pragma unroll
            for (int f = 0; f < 4; ++f) {
                const float pb0 = pbuf[s][2 * f],     pl0 = plbuf[s][2 * f];
                const float pb1 = pbuf[s][2 * f + 1], pl1 = plbuf[s][2 * f + 1];

                // boundary zeroing of shuffled VALUES (out-of-range shfl
                // returns own value; exponents are auto-neutral: s_pe = own e)
                const float b1o_r = z1 ? 0.0f : s_no1;
                const float b1e_r = z1 ? 0.0f : s_ne1;
                const float b2o_r = z2 ? 0.0f : s_no2;

                // anchor from POST-rescale exponents only (one-step stale max)
                const int en = max(e, max(s_pe1, s_pe2));
                const int d0 = max(e     - en, -127);
                const int d1 = max(s_en1 - en, -127);   // may be > 0, <= 127
                const int d2 = max(s_en2 - en, -127);
                const float f0 = __int_as_float((127 + d0) << 23);  // 2^d0
                const float f1 = __int_as_float((127 + d1) << 23);  // 2^d1
                const float f2 = __int_as_float((127 + d2) << 23);  // 2^d2

                const float ae  = me * f0;      // a[2l]
                const float ao  = mo * f0;      // a[2l+1]
                const float b1o = b1o_r * f1;   // a[2l-1]
                const float b1e = b1e_r * f1;   // a[2l-2]
                const float b2o = b2o_r * f2;   // a[2l-3]

                // ---- fused two-timestep DP ----
                //   A1[2l]   = (a[2l] + a[2l-1]) * pb0              = B0*pb0
                //   A1[2l+1] = (a[2l+1]+a[2l]+sk*a[2l-1]) * pl0     = A1o*pl0
                //   A1[2l-1] = (a[2l-1]+a[2l-2]+skm*a[2l-3]) * plm  = A1m*plm
                const float B0  = ae + b1o;
                const float A1o = fmaf(sk,  b1o, ao + ae);
                const float A1m = fmaf(skm, b2o, b1o + b1e);
                const float t1e = B0  * pb0;    // A1[2l]
                const float t2e = A1m * s_plm;  // A1[2l-1]
                const float t3  = A1o * pl0;    // A1[2l+1]
                // after t1:
                const float ne  = (t1e + t2e) * pb1;
                const float no  = fmaf(sk, t2e, t3 + t1e) * pl1;
                const float u   = fmaf(a64, f0, ao) * pb0;   // A1[64] (lane31)
                const float n64 = (u + t3) * pb1;

                // post-rescale exponent for THIS iteration (needed pre-shuffle)
                const float m64 = l31 ? n64 : 0.0f;
                const float mx  = fmaxf(fmaxf(ne, no), m64);
                const int   ex  = (__float_as_int(mx) >> 23) - 127;
                const int   ep  = en + ex;      // true lane magnitude

                // issue next-iteration shuffles
                const float nxt_pl0 = (f < 3) ? plbuf[s][2 * f + 2]
                                              : plbuf[(s + 1) & 3][0];
                s_no1 = __shfl_up_sync(FULLMASK, no, 1);
                s_ne1 = __shfl_up_sync(FULLMASK, ne, 1);
                s_no2 = __shfl_up_sync(FULLMASK, no, 2);
                s_en1 = __shfl_up_sync(FULLMASK, en, 1);
                s_en2 = __shfl_up_sync(FULLMASK, en, 2);
                s_pe1 = __shfl_up_sync(FULLMASK, ep, 1);
                s_pe2 = __shfl_up_sync(FULLMASK, ep, 2);
                s_plm = __shfl_up_sync(FULLMASK, nxt_pl0, 1);

                // mantissa rescale (runs in the shuffle latency shadow)
                const float rr = __int_as_float((127 - ex) << 23);  // 2^-ex
                me  = ne  * rr;
                mo  = no  * rr;
                a64 = n64 * rr;
                e   = ep;
            }
        }
    }

    // loss = -ln(alpha_T[64] + alpha_T[63]); both on lane 31 at scale 2^e
    if (l31) {
        const float msum = a64 + mo;
        out[b] = -(((float)e + log2f(msum)) * 0.69314718055994530942f);
    }
}

extern "C" void kernel_launch(void* const* d_in, const int* in_sizes, int n_in,
                              void* d_out, int out_size) {
    const int*   y_true;
    const float* y_pred;
    // identify inputs by size (y_true = 512*32 int32, y_pred = 512*512*128 f32)
    if (in_sizes[0] == Bn * Ln) {
        y_true = (const int*)d_in[0];
        y_pred = (const float*)d_in[1];
    } else {
        y_true = (const int*)d_in[1];
        y_pred = (const float*)d_in[0];
    }
    ctc_fwd_kernel<<<Bn, 32>>>(y_true, y_pred, (float*)d_out);
}

// round 15
// speedup vs baseline: 1.7197x; 1.5294x over previous
#include <cuda_runtime.h>

#define FULLMASK 0xFFFFFFFFu

constexpr int Bn = 512;   // batch
constexpr int Tn = 512;   // time steps
constexpr int Cn = 128;   // classes (blank = C-1 = 127)
constexpr int Ln = 32;    // label length  (S = 2L+1 = 65 states)
constexpr int TS = 256;   // timesteps per direction (T/2)
constexpr float EPSF = 1e-7f;

// Forward-backward split: L = sum_s alpha_255[s] * beta_255[s].
// Warp 0 computes alpha over t=0..255 (forward). Warp 1 computes beta over
// t=511..256 via the EXACT same recurrence on (reversed time, reversed
// labels) with state mapping s_hat = 64-s:
//   h_tau[s_hat] = lp_{511-tau}[ext[64-s_hat]] * gamma_tau[s_hat]
// obeys h_tau = gather(h_{tau-1}) * lp(own state, time 511-tau) — identical
// to the forward delta-init recurrence. One final gather-only step yields
// gamma_256[s_hat] = beta_255[64-s_hat]. Combine via smem in original
// state coordinates.
//
// Inner loop: linear-domain DP, per-lane block floating point, TWO fused
// timesteps per update. Anchor formed from POST-rescale exponents only
// (true lane magnitudes, one-step stale) while shuffled PRE-rescale
// mantissas carry their own anchor `en` for value reconstruction.
__global__ __launch_bounds__(64, 8)
void ctc_fwd_kernel(const int* __restrict__ y_true,
                    const float* __restrict__ y_pred,
                    float* __restrict__ out)
{
    const int b    = blockIdx.x;
    const int tid  = threadIdx.x;
    const int w    = tid >> 5;              // 0 = forward, 1 = backward
    const int lane = tid & 31;

    __shared__ float smA_m[65], smB_m[65];
    __shared__ int   smA_e[65], smB_e[65];

    // labels: forward uses y_true[lane]; backward uses reversed labels
    const int   labidx   = (w == 0) ? lane : (31 - lane);
    const int   lab      = y_true[b * Ln + labidx];
    const int   lab_prev = __shfl_up_sync(FULLMASK, lab, 1);
    const float sk       = (lane > 0 && lab != lab_prev) ? 1.0f : 0.0f;
    const float skm      = __shfl_up_sync(FULLMASK, sk, 1);
    const bool  z1 = (lane == 0);
    const bool  z2 = (lane < 2);
    const bool  l31 = (lane == 31);

    const float* __restrict__ row = y_pred + (size_t)b * Tn * Cn;
    // step g (0..255) consumes time: fwd g, bwd 511-g
    const int t0   = (w == 0) ? 0 : (Tn - 1);
    const int tdir = (w == 0) ? 1 : -1;

    // Ring prefetch: 4 slots x 8 timesteps, distance 24 steps.
    float pbuf[4][8], plbuf[4][8];
    #pragma unroll
    for (int s = 0; s < 3; ++s)
        #pragma unroll
        for (int j = 0; j < 8; ++j) {
            const float* r = row + (size_t)(t0 + tdir * (s * 8 + j)) * Cn;
            pbuf[s][j]  = __ldcs(r + (Cn - 1)) + EPSF;
            plbuf[s][j] = __ldcs(r + lab)      + EPSF;
        }

    // Delta-init: state_{-1} = delta at own state 0.
    float me  = z1 ? 1.0f : 0.0f;
    float mo  = 0.0f;
    float a64 = 0.0f;
    int   e   = 0;

    float s_no1 = __shfl_up_sync(FULLMASK, mo, 1);
    float s_ne1 = __shfl_up_sync(FULLMASK, me, 1);
    float s_no2 = __shfl_up_sync(FULLMASK, mo, 2);
    int   s_en1 = __shfl_up_sync(FULLMASK, e, 1);
    int   s_en2 = __shfl_up_sync(FULLMASK, e, 2);
    int   s_pe1 = __shfl_up_sync(FULLMASK, e, 1);
    int   s_pe2 = __shfl_up_sync(FULLMASK, e, 2);
    float s_plm = __shfl_up_sync(FULLMASK, plbuf[0][0], 1);

    for (int big = 0; big < 8; ++big) {
        #pragma unroll
        for (int s = 0; s < 4; ++s) {
            const int gld = (big * 4 + s) * 8 + 24;
            if (gld < TS) {
                const int ls = (s + 3) & 3;
                #pragma unroll
                for (int j = 0; j < 8; ++j) {
                    const float* r = row + (size_t)(t0 + tdir * (gld + j)) * Cn;
                    pbuf[ls][j]  = __ldcs(r + (Cn - 1)) + EPSF;
                    plbuf[ls][j] = __ldcs(r + lab)      + EPSF;
                }
            }

            #pragma unroll
            for (int f = 0; f < 4; ++f) {
                const float pb0 = pbuf[s][2 * f],     pl0 = plbuf[s][2 * f];
                const float pb1 = pbuf[s][2 * f + 1], pl1 = plbuf[s][2 * f + 1];

                const float b1o_r = z1 ? 0.0f : s_no1;
                const float b1e_r = z1 ? 0.0f : s_ne1;
                const float b2o_r = z2 ? 0.0f : s_no2;

                // anchor from POST-rescale exponents (one-step stale max)
                const int en = max(e, max(s_pe1, s_pe2));
                const int d0 = max(e     - en, -127);
                const int d1 = max(s_en1 - en, -127);
                const int d2 = max(s_en2 - en, -127);
                const float f0 = __int_as_float((127 + d0) << 23);
                const float f1 = __int_as_float((127 + d1) << 23);
                const float f2 = __int_as_float((127 + d2) << 23);

                const float ae  = me * f0;
                const float ao  = mo * f0;
                const float b1o = b1o_r * f1;
                const float b1e = b1e_r * f1;
                const float b2o = b2o_r * f2;

                // fused two-timestep DP
                const float B0  = ae + b1o;
                const float A1o = fmaf(sk,  b1o, ao + ae);
                const float A1m = fmaf(skm, b2o, b1o + b1e);
                const float t1e = B0  * pb0;
                const float t2e = A1m * s_plm;
                const float t3  = A1o * pl0;
                const float ne  = (t1e + t2e) * pb1;
                const float no  = fmaf(sk, t2e, t3 + t1e) * pl1;
                const float u   = fmaf(a64, f0, ao) * pb0;
                const float n64 = (u + t3) * pb1;

                const float m64 = l31 ? n64 : 0.0f;
                const float mx  = fmaxf(fmaxf(ne, no), m64);
                const int   ex  = (__float_as_int(mx) >> 23) - 127;
                const int   ep  = en + ex;

                const float nxt_pl0 = (f < 3) ? plbuf[s][2 * f + 2]
                                              : plbuf[(s + 1) & 3][0];
                s_no1 = __shfl_up_sync(FULLMASK, no, 1);
                s_ne1 = __shfl_up_sync(FULLMASK, ne, 1);
                s_no2 = __shfl_up_sync(FULLMASK, no, 2);
                s_en1 = __shfl_up_sync(FULLMASK, en, 1);
                s_en2 = __shfl_up_sync(FULLMASK, en, 2);
                s_pe1 = __shfl_up_sync(FULLMASK, ep, 1);
                s_pe2 = __shfl_up_sync(FULLMASK, ep, 2);
                s_plm = __shfl_up_sync(FULLMASK, nxt_pl0, 1);

                const float rr = __int_as_float((127 - ex) << 23);
                me  = ne  * rr;
                mo  = no  * rr;
                a64 = n64 * rr;
                e   = ep;
            }
        }
    }

    // Backward warp: final gather-only step -> gamma_256 (no lp multiply)
    if (w == 1) {
        float mo1 = __shfl_up_sync(FULLMASK, mo, 1);
        int   e1  = __shfl_up_sync(FULLMASK, e, 1);
        if (z1) { mo1 = 0.0f; e1 = e; }
        const int en = max(e, e1);
        const float f0 = __int_as_float((127 + max(e  - en, -127)) << 23);
        const float f1 = __int_as_float((127 + max(e1 - en, -127)) << 23);
        const float he = me * f0, ho = mo * f0, h1 = mo1 * f1;
        const float ge  = he + h1;                    // gamma[2l^]
        const float go  = fmaf(sk, h1, ho + he);      // gamma[2l^+1]
        const float g64 = fmaf(a64, f0, ho);          // gamma[64] (lane 31)
        me = ge; mo = go; a64 = g64; e = en;
    }

    // Dump states in ORIGINAL state coordinates
    if (w == 0) {
        smA_m[2 * lane]     = me;  smA_e[2 * lane]     = e;
        smA_m[2 * lane + 1] = mo;  smA_e[2 * lane + 1] = e;
        if (l31) { smA_m[64] = a64; smA_e[64] = e; }
    } else {
        smB_m[64 - 2 * lane] = me;  smB_e[64 - 2 * lane] = e;
        smB_m[63 - 2 * lane] = mo;  smB_e[63 - 2 * lane] = e;
        if (l31) { smB_m[0] = a64; smB_e[0] = e; }
    }
    __syncthreads();

    // Combine: L = sum_s alpha[s]*beta[s] in block floating point
    if (w == 0) {
        const float p0 = smA_m[2 * lane]     * smB_m[2 * lane];
        const float p1 = smA_m[2 * lane + 1] * smB_m[2 * lane + 1];
        const float p2 = l31 ? (smA_m[64] * smB_m[64]) : 0.0f;
        int q0 = smA_e[2 * lane]     + smB_e[2 * lane];
        int q1 = smA_e[2 * lane + 1] + smB_e[2 * lane + 1];
        int q2 = l31 ? (smA_e[64] + smB_e[64]) : 0;
        const int NEGQ = -(1 << 28);
        if (p0 == 0.0f) q0 = NEGQ;
        if (p1 == 0.0f) q1 = NEGQ;
        if (p2 == 0.0f) q2 = NEGQ;

        int qm = max(q0, max(q1, q2));
        #pragma unroll
        for (int off = 16; off > 0; off >>= 1)
            qm = max(qm, __shfl_xor_sync(FULLMASK, qm, off));

        const float g0 = __int_as_float((127 + max(q0 - qm, -127)) << 23);
        const float g1 = __int_as_float((127 + max(q1 - qm, -127)) << 23);
        const float g2 = __int_as_float((127 + max(q2 - qm, -127)) << 23);
        float v = p0 * g0 + p1 * g1 + p2 * g2;
        #pragma unroll
        for (int off = 16; off > 0; off >>= 1)
            v += __shfl_xor_sync(FULLMASK, v, off);

        if (lane == 0)
            out[b] = -(((float)qm + log2f(v)) * 0.69314718055994530942f);
    }
}

extern "C" void kernel_launch(void* const* d_in, const int* in_sizes, int n_in,
                              void* d_out, int out_size) {
    const int*   y_true;
    const float* y_pred;
    // identify inputs by size (y_true = 512*32 int32, y_pred = 512*512*128 f32)
    if (in_sizes[0] == Bn * Ln) {
        y_true = (const int*)d_in[0];
        y_pred = (const float*)d_in[1];
    } else {
        y_true = (const int*)d_in[1];
        y_pred = (const float*)d_in[0];
    }
    ctc_fwd_kernel<<<Bn, 64>>>(y_true, y_pred, (float*)d_out);
}

// round 16
// speedup vs baseline: 1.7454x; 1.0149x over previous
#include <cuda_runtime.h>

#define FULLMASK 0xFFFFFFFFu

constexpr int Bn = 512;   // batch
constexpr int Tn = 512;   // time steps
constexpr int Cn = 128;   // classes (blank = C-1 = 127)
constexpr int Ln = 32;    // label length  (S = 2L+1 = 65 states)
constexpr int TS = 256;   // timesteps per direction (T/2)
constexpr float EPSF = 1e-7f;

// Forward-backward split: L = sum_s alpha_255[s] * beta_255[s].
// Warp 0 computes alpha over t=0..255 (forward). Warp 1 computes beta over
// t=511..256 via the same recurrence on (reversed time, reversed labels)
// with state mapping s_hat = 64-s, plus one final gather-only step.
//
// Inner loop: linear-domain DP, per-lane block floating point, TWO fused
// timesteps per update. Anchor formed from POST-rescale exponents only.
//
// __launch_bounds__(64, 4): the grid only reaches ~3.5 resident blocks/SM,
// so capping at 4 loses nothing — but it doubles the register budget to 256
// and removes the ring-buffer spills that the (64,8)/128-reg build suffered
// (regs==cap exactly; ~500 cyc/iter vs ~100-cyc chain model).
__global__ __launch_bounds__(64, 4)
void ctc_fwd_kernel(const int* __restrict__ y_true,
                    const float* __restrict__ y_pred,
                    float* __restrict__ out)
{
    const int b    = blockIdx.x;
    const int tid  = threadIdx.x;
    const int w    = tid >> 5;              // 0 = forward, 1 = backward
    const int lane = tid & 31;

    __shared__ float smA_m[65], smB_m[65];
    __shared__ int   smA_e[65], smB_e[65];

    // labels: forward uses y_true[lane]; backward uses reversed labels
    const int   labidx   = (w == 0) ? lane : (31 - lane);
    const int   lab      = y_true[b * Ln + labidx];
    const int   lab_prev = __shfl_up_sync(FULLMASK, lab, 1);
    const float sk       = (lane > 0 && lab != lab_prev) ? 1.0f : 0.0f;
    const float skm      = __shfl_up_sync(FULLMASK, sk, 1);
    const bool  z1 = (lane == 0);
    const bool  z2 = (lane < 2);
    const bool  l31 = (lane == 31);

    const float* __restrict__ row = y_pred + (size_t)b * Tn * Cn;
    // step g (0..255) consumes time: fwd g, bwd 511-g
    const int t0   = (w == 0) ? 0 : (Tn - 1);
    const int tdir = (w == 0) ? 1 : -1;

    // Ring prefetch: 4 slots x 8 timesteps, distance 24 steps.
    float pbuf[4][8], plbuf[4][8];
    #pragma unroll
    for (int s = 0; s < 3; ++s)
        #pragma unroll
        for (int j = 0; j < 8; ++j) {
            const float* r = row + (size_t)(t0 + tdir * (s * 8 + j)) * Cn;
            pbuf[s][j]  = __ldcs(r + (Cn - 1)) + EPSF;
            plbuf[s][j] = __ldcs(r + lab)      + EPSF;
        }

    // Delta-init: state_{-1} = delta at own state 0.
    float me  = z1 ? 1.0f : 0.0f;
    float mo  = 0.0f;
    float a64 = 0.0f;
    int   e   = 0;

    float s_no1 = __shfl_up_sync(FULLMASK, mo, 1);
    float s_ne1 = __shfl_up_sync(FULLMASK, me, 1);
    float s_no2 = __shfl_up_sync(FULLMASK, mo, 2);
    int   s_en1 = __shfl_up_sync(FULLMASK, e, 1);
    int   s_en2 = __shfl_up_sync(FULLMASK, e, 2);
    int   s_pe1 = __shfl_up_sync(FULLMASK, e, 1);
    int   s_pe2 = __shfl_up_sync(FULLMASK, e, 2);
    float s_plm = __shfl_up_sync(FULLMASK, plbuf[0][0], 1);

    for (int big = 0; big < 8; ++big) {
        #pragma unroll
        for (int s = 0; s < 4; ++s) {
            const int gld = (big * 4 + s) * 8 + 24;
            if (gld < TS) {
                const int ls = (s + 3) & 3;
                #pragma unroll
                for (int j = 0; j < 8; ++j) {
                    const float* r = row + (size_t)(t0 + tdir * (gld + j)) * Cn;
                    pbuf[ls][j]  = __ldcs(r + (Cn - 1)) + EPSF;
                    plbuf[ls][j] = __ldcs(r + lab)      + EPSF;
                }
            }

            #pragma unroll
            for (int f = 0; f < 4; ++f) {
                const float pb0 = pbuf[s][2 * f],     pl0 = plbuf[s][2 * f];
                const float pb1 = pbuf[s][2 * f + 1], pl1 = plbuf[s][2 * f + 1];
                // ring peek for next iteration's neighbor label prob
                // (hoisted off the chain; f==3 reads the slot refilled 8
                //  timesteps from now only on the NEXT s, never this one)
                const float nxt_pl0 = (f < 3) ? plbuf[s][2 * f + 2]
                                              : plbuf[(s + 1) & 3][0];

                const float b1o_r = z1 ? 0.0f : s_no1;
                const float b1e_r = z1 ? 0.0f : s_ne1;
                const float b2o_r = z2 ? 0.0f : s_no2;

                // anchor from POST-rescale exponents (one-step stale max)
                const int en = max(e, max(s_pe1, s_pe2));
                const int d0 = max(e     - en, -127);
                const int d1 = max(s_en1 - en, -127);
                const int d2 = max(s_en2 - en, -127);
                const float f0 = __int_as_float((127 + d0) << 23);
                const float f1 = __int_as_float((127 + d1) << 23);
                const float f2 = __int_as_float((127 + d2) << 23);

                const float ae  = me * f0;
                const float ao  = mo * f0;
                const float b1o = b1o_r * f1;
                const float b1e = b1e_r * f1;
                const float b2o = b2o_r * f2;

                // fused two-timestep DP
                const float B0  = ae + b1o;
                const float A1o = fmaf(sk,  b1o, ao + ae);
                const float A1m = fmaf(skm, b2o, b1o + b1e);
                const float t1e = B0  * pb0;
                const float t2e = A1m * s_plm;
                const float t3  = A1o * pl0;
                const float ne  = (t1e + t2e) * pb1;
                const float no  = fmaf(sk, t2e, t3 + t1e) * pl1;
                const float u   = fmaf(a64, f0, ao) * pb0;
                const float n64 = (u + t3) * pb1;

                const float m64 = l31 ? n64 : 0.0f;
                const float mx  = fmaxf(fmaxf(ne, no), m64);
                const int   ex  = (__float_as_int(mx) >> 23) - 127;
                const int   ep  = en + ex;

                s_no1 = __shfl_up_sync(FULLMASK, no, 1);
                s_ne1 = __shfl_up_sync(FULLMASK, ne, 1);
                s_no2 = __shfl_up_sync(FULLMASK, no, 2);
                s_en1 = __shfl_up_sync(FULLMASK, en, 1);
                s_en2 = __shfl_up_sync(FULLMASK, en, 2);
                s_pe1 = __shfl_up_sync(FULLMASK, ep, 1);
                s_pe2 = __shfl_up_sync(FULLMASK, ep, 2);
                s_plm = __shfl_up_sync(FULLMASK, nxt_pl0, 1);

                const float rr = __int_as_float((127 - ex) << 23);
                me  = ne  * rr;
                mo  = no  * rr;
                a64 = n64 * rr;
                e   = ep;
            }
        }
    }

    // Backward warp: final gather-only step -> gamma_256 (no lp multiply)
    if (w == 1) {
        float mo1 = __shfl_up_sync(FULLMASK, mo, 1);
        int   e1  = __shfl_up_sync(FULLMASK, e, 1);
        if (z1) { mo1 = 0.0f; e1 = e; }
        const int en = max(e, e1);
        const float f0 = __int_as_float((127 + max(e  - en, -127)) << 23);
        const float f1 = __int_as_float((127 + max(e1 - en, -127)) << 23);
        const float he = me * f0, ho = mo * f0, h1 = mo1 * f1;
        const float ge  = he + h1;                    // gamma[2l^]
        const float go  = fmaf(sk, h1, ho + he);      // gamma[2l^+1]
        const float g64 = fmaf(a64, f0, ho);          // gamma[64] (lane 31)
        me = ge; mo = go; a64 = g64; e = en;
    }

    // Dump states in ORIGINAL state coordinates
    if (w == 0) {
        smA_m[2 * lane]     = me;  smA_e[2 * lane]     = e;
        smA_m[2 * lane + 1] = mo;  smA_e[2 * lane + 1] = e;
        if (l31) { smA_m[64] = a64; smA_e[64] = e; }
    } else {
        smB_m[64 - 2 * lane] = me;  smB_e[64 - 2 * lane] = e;
        smB_m[63 - 2 * lane] = mo;  smB_e[63 - 2 * lane] = e;
        if (l31) { smB_m[0] = a64; smB_e[0] = e; }
    }
    __syncthreads();

    // Combine: L = sum_s alpha[s]*beta[s] in block floating point
    if (w == 0) {
        const float p0 = smA_m[2 * lane]     * smB_m[2 * lane];
        const float p1 = smA_m[2 * lane + 1] * smB_m[2 * lane + 1];
        const float p2 = l31 ? (smA_m[64] * smB_m[64]) : 0.0f;
        int q0 = smA_e[2 * lane]     + smB_e[2 * lane];
        int q1 = smA_e[2 * lane + 1] + smB_e[2 * lane + 1];
        int q2 = l31 ? (smA_e[64] + smB_e[64]) : 0;
        const int NEGQ = -(1 << 28);
        if (p0 == 0.0f) q0 = NEGQ;
        if (p1 == 0.0f) q1 = NEGQ;
        if (p2 == 0.0f) q2 = NEGQ;

        int qm = max(q0, max(q1, q2));
        #pragma unroll
        for (int off = 16; off > 0; off >>= 1)
            qm = max(qm, __shfl_xor_sync(FULLMASK, qm, off));

        const float g0 = __int_as_float((127 + max(q0 - qm, -127)) << 23);
        const float g1 = __int_as_float((127 + max(q1 - qm, -127)) << 23);
        const float g2 = __int_as_float((127 + max(q2 - qm, -127)) << 23);
        float v = p0 * g0 + p1 * g1 + p2 * g2;
        #pragma unroll
        for (int off = 16; off > 0; off >>= 1)
            v += __shfl_xor_sync(FULLMASK, v, off);

        if (lane == 0)
            out[b] = -(((float)qm + log2f(v)) * 0.69314718055994530942f);
    }
}

extern "C" void kernel_launch(void* const* d_in, const int* in_sizes, int n_in,
                              void* d_out, int out_size) {
    const int*   y_true;
    const float* y_pred;
    // identify inputs by size (y_true = 512*32 int32, y_pred = 512*512*128 f32)
    if (in_sizes[0] == Bn * Ln) {
        y_true = (const int*)d_in[0];
        y_pred = (const float*)d_in[1];
    } else {
        y_true = (const int*)d_in[1];
        y_pred = (const float*)d_in[0];
    }
    ctc_fwd_kernel<<<Bn, 64>>>(y_true, y_pred, (float*)d_out);
}

// round 17
// speedup vs baseline: 2.2413x; 1.2841x over previous
#include <cuda_runtime.h>

#define FULLMASK 0xFFFFFFFFu

constexpr int Bn = 512;   // batch
constexpr int Tn = 512;   // time steps
constexpr int Cn = 128;   // classes (blank = C-1 = 127)
constexpr int Ln = 32;    // label length  (S = 2L+1 = 65 states)
constexpr int TS = 256;   // timesteps per direction (T/2)
constexpr float EPSF = 1e-7f;
constexpr int EBIAS = 8192;   // exponent bias so packed fields stay positive

__device__ __forceinline__ unsigned smem_u32(const void* p) {
    return (unsigned)__cvta_generic_to_shared(p);
}
__device__ __forceinline__ void cp_async4(unsigned s, const float* g) {
    asm volatile("cp.async.ca.shared.global [%0], [%1], 4;" :: "r"(s), "l"(g));
}
#define CP_COMMIT() asm volatile("cp.async.commit_group;" ::: "memory")
#define CP_WAIT3()  asm volatile("cp.async.wait_group 3;" ::: "memory")

// Forward-backward split (L = sum_s alpha_255[s]*beta_255[s]); warp 0 forward
// t=0..255, warp 1 backward t=511..256 on reversed labels (s_hat=64-s), one
// final gather-only step. Per-lane block floating point, 2 fused timesteps
// per update, anchor from POST-rescale exponents.
//
// Operand delivery rebuilt around cp.async -> SMEM ring (4 slots x 8 t):
// commit-group per refill + wait_group 3 gives PRECISE completion tracking,
// removing the SASS scoreboard false-sharing stalls that register-ring LDG
// prefetch suffers (16 loads packed on ~3 shared wbar slots -> every consume
// waited on the newest refill). Also: plm comes from SMEM[lane-1] (one less
// shuffle) and en/ep are bias-packed into one shuffled int (two less).
__global__ __launch_bounds__(64, 4)
void ctc_fwd_kernel(const int* __restrict__ y_true,
                    const float* __restrict__ y_pred,
                    float* __restrict__ out)
{
    const int b    = blockIdx.x;
    const int tid  = threadIdx.x;
    const int w    = tid >> 5;              // 0 = forward, 1 = backward
    const int lane = tid & 31;

    __shared__ float stage[2][4][8][33];    // [warp][slot][t][lane<32 pl | 32=pb]
    __shared__ float smA_m[65], smB_m[65];
    __shared__ int   smA_e[65], smB_e[65];

    const int   labidx   = (w == 0) ? lane : (31 - lane);
    const int   lab      = y_true[b * Ln + labidx];
    const int   lab_prev = __shfl_up_sync(FULLMASK, lab, 1);
    const float sk       = (lane > 0 && lab != lab_prev) ? 1.0f : 0.0f;
    const float skm      = __shfl_up_sync(FULLMASK, sk, 1);
    const bool  z1 = (lane == 0);
    const bool  z2 = (lane < 2);
    const bool  l31 = (lane == 31);
    const int   li  = z1 ? 0 : (lane - 1);  // plm source (lane0 value unused)

    const float* __restrict__ row = y_pred + (size_t)b * Tn * Cn;
    const int t0   = (w == 0) ? 0 : (Tn - 1);
    const int tdir = (w == 0) ? 1 : -1;

    const unsigned sb = smem_u32(&stage[w][0][0][0]);
    const float* srow = &stage[w][0][0][0];

    // Prologue: fill slots 0..2 (timesteps 0..23), one commit group each.
    for (int sl = 0; sl < 3; ++sl) {
        const int tb = sl * 8;
        #pragma unroll
        for (int j = 0; j < 8; ++j)
            cp_async4(sb + ((sl * 8 + j) * 33 + lane) * 4u,
                      row + (size_t)(t0 + tdir * (tb + j)) * Cn + lab);
        if (lane < 8)
            cp_async4(sb + ((sl * 8 + lane) * 33 + 32) * 4u,
                      row + (size_t)(t0 + tdir * (tb + lane)) * Cn + (Cn - 1));
        CP_COMMIT();
    }

    // Delta-init: state_{-1} = delta at own state 0.
    float me  = z1 ? 1.0f : 0.0f;
    float mo  = 0.0f;
    float a64 = 0.0f;
    int   e_b = EBIAS;                      // biased post-rescale exponent

    float s_no1 = __shfl_up_sync(FULLMASK, mo, 1);
    float s_ne1 = __shfl_up_sync(FULLMASK, me, 1);
    float s_no2 = __shfl_up_sync(FULLMASK, mo, 2);
    const int pk0 = (e_b << 16) | e_b;      // (en_b, ep_b) packed
    int s_pk1 = __shfl_up_sync(FULLMASK, pk0, 1);
    int s_pk2 = __shfl_up_sync(FULLMASK, pk0, 2);

    for (int big = 0; big < 8; ++big) {
        #pragma unroll
        for (int s4 = 0; s4 < 4; ++s4) {
            // refill slot (s4+3)&3 with timesteps gld..gld+7, then wait for
            // the group 3 refills back (slot s4) — precise, no false waits.
            const int gld = (big * 4 + s4) * 8 + 24;
            const int ls  = (s4 + 3) & 3;
            if (gld < TS) {
                #pragma unroll
                for (int j = 0; j < 8; ++j)
                    cp_async4(sb + ((ls * 8 + j) * 33 + lane) * 4u,
                              row + (size_t)(t0 + tdir * (gld + j)) * Cn + lab);
                if (lane < 8)
                    cp_async4(sb + ((ls * 8 + lane) * 33 + 32) * 4u,
                              row + (size_t)(t0 + tdir * (gld + lane)) * Cn + (Cn - 1));
            }
            CP_COMMIT();
            CP_WAIT3();
            __syncwarp();

            const float* slot = srow + s4 * 8 * 33;
            float cpb0 = slot[0 * 33 + 32]   + EPSF;
            float cpb1 = slot[1 * 33 + 32]   + EPSF;
            float cpl0 = slot[0 * 33 + lane] + EPSF;
            float cpl1 = slot[1 * 33 + lane] + EPSF;
            float cplm = slot[0 * 33 + li]   + EPSF;

            #pragma unroll
            for (int f = 0; f < 4; ++f) {
                // LDS prefetch for next fused iteration (within this slot)
                float npb0, npb1, npl0, npl1, nplm;
                if (f < 3) {
                    npb0 = slot[(2 * f + 2) * 33 + 32]   + EPSF;
                    npb1 = slot[(2 * f + 3) * 33 + 32]   + EPSF;
                    npl0 = slot[(2 * f + 2) * 33 + lane] + EPSF;
                    npl1 = slot[(2 * f + 3) * 33 + lane] + EPSF;
                    nplm = slot[(2 * f + 2) * 33 + li]   + EPSF;
                }

                const float b1o_r = z1 ? 0.0f : s_no1;
                const float b1e_r = z1 ? 0.0f : s_ne1;
                const float b2o_r = z2 ? 0.0f : s_no2;

                // unpack neighbor exponents (biased; out-of-range lanes
                // return own pk: pe == own e_b -> neutral in the max)
                const int en1 = s_pk1 >> 16, pe1 = s_pk1 & 0xFFFF;
                const int en2 = s_pk2 >> 16, pe2 = s_pk2 & 0xFFFF;
                const int en  = max(e_b, max(pe1, pe2));
                const int d0  = max(e_b - en, -127);
                const int d1  = max(en1 - en, -127);
                const int d2  = max(en2 - en, -127);
                const float f0 = __int_as_float((127 + d0) << 23);
                const float f1 = __int_as_float((127 + d1) << 23);
                const float f2 = __int_as_float((127 + d2) << 23);

                const float ae  = me * f0;
                const float ao  = mo * f0;
                const float b1o = b1o_r * f1;
                const float b1e = b1e_r * f1;
                const float b2o = b2o_r * f2;

                // fused two-timestep DP
                const float B0  = ae + b1o;
                const float A1o = fmaf(sk,  b1o, ao + ae);
                const float A1m = fmaf(skm, b2o, b1o + b1e);
                const float t1e = B0  * cpb0;
                const float t2e = A1m * cplm;
                const float t3  = A1o * cpl0;
                const float ne  = (t1e + t2e) * cpb1;
                const float no  = fmaf(sk, t2e, t3 + t1e) * cpl1;
                const float u   = fmaf(a64, f0, ao) * cpb0;
                const float n64 = (u + t3) * cpb1;

                const float m64 = l31 ? n64 : 0.0f;
                const float mx  = fmaxf(fmaxf(ne, no), m64);
                const int   ex  = (__float_as_int(mx) >> 23) - 127;
                const int   ep  = en + ex;
                const int   pk  = (en << 16) | ep;

                s_no1 = __shfl_up_sync(FULLMASK, no, 1);
                s_ne1 = __shfl_up_sync(FULLMASK, ne, 1);
                s_no2 = __shfl_up_sync(FULLMASK, no, 2);
                s_pk1 = __shfl_up_sync(FULLMASK, pk, 1);
                s_pk2 = __shfl_up_sync(FULLMASK, pk, 2);

                const float rr = __int_as_float((127 - ex) << 23);
                me  = ne  * rr;
                mo  = no  * rr;
                a64 = n64 * rr;
                e_b = ep;

                if (f < 3) { cpb0 = npb0; cpb1 = npb1; cpl0 = npl0;
                             cpl1 = npl1; cplm = nplm; }
            }
        }
    }

    // Backward warp: final gather-only step (no lp multiply)
    if (w == 1) {
        float mo1 = __shfl_up_sync(FULLMASK, mo, 1);
        int   e1  = __shfl_up_sync(FULLMASK, e_b, 1);
        if (z1) { mo1 = 0.0f; e1 = e_b; }
        const int en = max(e_b, e1);
        const float f0 = __int_as_float((127 + max(e_b - en, -127)) << 23);
        const float f1 = __int_as_float((127 + max(e1  - en, -127)) << 23);
        const float he = me * f0, ho = mo * f0, h1 = mo1 * f1;
        const float ge  = he + h1;
        const float go  = fmaf(sk, h1, ho + he);
        const float g64 = fmaf(a64, f0, ho);
        me = ge; mo = go; a64 = g64; e_b = en;
    }

    // Dump states in ORIGINAL state coordinates (unbiased exponents)
    const int e_true = e_b - EBIAS;
    if (w == 0) {
        smA_m[2 * lane]     = me;  smA_e[2 * lane]     = e_true;
        smA_m[2 * lane + 1] = mo;  smA_e[2 * lane + 1] = e_true;
        if (l31) { smA_m[64] = a64; smA_e[64] = e_true; }
    } else {
        smB_m[64 - 2 * lane] = me;  smB_e[64 - 2 * lane] = e_true;
        smB_m[63 - 2 * lane] = mo;  smB_e[63 - 2 * lane] = e_true;
        if (l31) { smB_m[0] = a64; smB_e[0] = e_true; }
    }
    __syncthreads();

    // Combine: L = sum_s alpha[s]*beta[s] in block floating point
    if (w == 0) {
        const float p0 = smA_m[2 * lane]     * smB_m[2 * lane];
        const float p1 = smA_m[2 * lane + 1] * smB_m[2 * lane + 1];
        const float p2 = l31 ? (smA_m[64] * smB_m[64]) : 0.0f;
        int q0 = smA_e[2 * lane]     + smB_e[2 * lane];
        int q1 = smA_e[2 * lane + 1] + smB_e[2 * lane + 1];
        int q2 = l31 ? (smA_e[64] + smB_e[64]) : 0;
        const int NEGQ = -(1 << 28);
        if (p0 == 0.0f) q0 = NEGQ;
        if (p1 == 0.0f) q1 = NEGQ;
        if (p2 == 0.0f) q2 = NEGQ;

        int qm = max(q0, max(q1, q2));
        #pragma unroll
        for (int off = 16; off > 0; off >>= 1)
            qm = max(qm, __shfl_xor_sync(FULLMASK, qm, off));

        const float g0 = __int_as_float((127 + max(q0 - qm, -127)) << 23);
        const float g1 = __int_as_float((127 + max(q1 - qm, -127)) << 23);
        const float g2 = __int_as_float((127 + max(q2 - qm, -127)) << 23);
        float v = p0 * g0 + p1 * g1 + p2 * g2;
        #pragma unroll
        for (int off = 16; off > 0; off >>= 1)
            v += __shfl_xor_sync(FULLMASK, v, off);

        if (lane == 0)
            out[b] = -(((float)qm + log2f(v)) * 0.69314718055994530942f);
    }
}

extern "C" void kernel_launch(void* const* d_in, const int* in_sizes, int n_in,
                              void* d_out, int out_size) {
    const int*   y_true;
    const float* y_pred;
    // identify inputs by size (y_true = 512*32 int32, y_pred = 512*512*128 f32)
    if (in_sizes[0] == Bn * Ln) {
        y_true = (const int*)d_in[0];
        y_pred = (const float*)d_in[1];
    } else {
        y_true = (const int*)d_in[1];
        y_pred = (const float*)d_in[0];
    }
    ctc_fwd_kernel<<<Bn, 64>>>(y_true, y_pred, (float*)d_out);
}